// round 6
// baseline (speedup 1.0000x reference)
#include <cuda_runtime.h>
#include <cuda_fp16.h>

#define NMAX 100000
#define SLOT 64
#define FULLMASK 0xffffffffu

// Scratch (allocation-free)
__device__ float g_hn[NMAX * 64];                    // LN'd state fp32
__device__ __align__(16) __half g_hn16[NMAX * 64];   // LN'd state fp16 (gather operand)
__device__ float g_msg[NMAX * 64];                   // gathered messages
__device__ int  g_deg[NMAX];
__device__ int2 g_csr[(size_t)NMAX * SLOT];          // (src byte offset, w bits)

__device__ __forceinline__ float lrelu(float v) { return v >= 0.f ? v : 0.01f * v; }

// ---- packed f32x2 helpers (sm_103a) ---------------------------------------
__device__ __forceinline__ unsigned long long dup2(float v) {
    unsigned long long r;
    asm("mov.b64 %0, {%1, %1};" : "=l"(r) : "f"(v));
    return r;
}
__device__ __forceinline__ unsigned long long pack2(float a, float b) {
    unsigned long long r;
    asm("mov.b64 %0, {%1, %2};" : "=l"(r) : "f"(a), "f"(b));
    return r;
}
__device__ __forceinline__ void fma2(unsigned long long& acc, unsigned long long a,
                                     unsigned long long b) {
    asm("fma.rn.f32x2 %0, %1, %2, %0;" : "+l"(acc) : "l"(a), "l"(b));
}
__device__ __forceinline__ float2 unpack2(unsigned long long v) {
    float2 f;
    asm("mov.b64 {%0, %1}, %2;" : "=f"(f.x), "=f"(f.y) : "l"(v));
    return f;
}

// ---------------------------------------------------------------------------
// CSR fill (g_deg zeroed by enc_kernel, which runs first)
// ---------------------------------------------------------------------------
__global__ void fill_csr_kernel(const int* __restrict__ src, const int* __restrict__ dst,
                                const float* __restrict__ w, int ne) {
    int e = blockIdx.x * blockDim.x + threadIdx.x;
    if (e >= ne) return;
    int d = dst[e];
    int slot = atomicAdd(&g_deg[d], 1);
    if (slot < SLOT)
        g_csr[(size_t)d * SLOT + slot] = make_int2(src[e] * 128, __float_as_int(w[e]));
}

// ---------------------------------------------------------------------------
// Encoder + LN(layer 0), THREAD per node. Also zeroes g_deg for fill_csr.
// ---------------------------------------------------------------------------
__global__ void __launch_bounds__(256, 2)
enc_kernel(const float* __restrict__ x,
           const float* __restrict__ W1, const float* __restrict__ b1,
           const float* __restrict__ W2, const float* __restrict__ b2,
           const float* __restrict__ lg, const float* __restrict__ lb, int n) {
    __shared__ __align__(16) float sW1T[128 * 16];  // [k][j] = W1[j][k]
    __shared__ __align__(16) float sW2[128 * 64];
    __shared__ float sb1[128];
    __shared__ __align__(16) float sb2[64];
    __shared__ float sg[64], sbb[64];
    for (int i = threadIdx.x; i < 2048; i += 256) {
        int j = i >> 7, k = i & 127;
        sW1T[k * 16 + j] = W1[i];
    }
    for (int i = threadIdx.x; i < 8192; i += 256) sW2[i] = W2[i];
    if (threadIdx.x < 128) sb1[threadIdx.x] = b1[threadIdx.x];
    if (threadIdx.x < 64) {
        sb2[threadIdx.x] = b2[threadIdx.x];
        sg[threadIdx.x]  = lg[threadIdx.x];
        sbb[threadIdx.x] = lb[threadIdx.x];
    }
    __syncthreads();

    int i = blockIdx.x * 256 + threadIdx.x;
    if (i >= n) return;
    g_deg[i] = 0;   // prepare for fill_csr_kernel

    float xr[16];
    const float4* xp = reinterpret_cast<const float4*>(x + (size_t)i * 16);
    #pragma unroll
    for (int q = 0; q < 4; q++) {
        float4 v = xp[q];
        xr[4 * q] = v.x; xr[4 * q + 1] = v.y; xr[4 * q + 2] = v.z; xr[4 * q + 3] = v.w;
    }

    unsigned long long o2[32];
    const unsigned long long* sb2p = reinterpret_cast<const unsigned long long*>(sb2);
    #pragma unroll
    for (int j = 0; j < 32; j++) o2[j] = sb2p[j];

    #pragma unroll 8
    for (int k = 0; k < 128; k++) {
        const float4* c = reinterpret_cast<const float4*>(sW1T + k * 16);
        float t = sb1[k];
        #pragma unroll
        for (int q = 0; q < 4; q++) {
            float4 wv = c[q];
            t += wv.x * xr[4 * q] + wv.y * xr[4 * q + 1]
               + wv.z * xr[4 * q + 2] + wv.w * xr[4 * q + 3];
        }
        t = lrelu(t);
        unsigned long long tk = dup2(t);
        const ulonglong2* row = reinterpret_cast<const ulonglong2*>(sW2 + k * 64);
        #pragma unroll
        for (int j = 0; j < 16; j++) {
            ulonglong2 p = row[j];
            fma2(o2[2 * j],     tk, p.x);
            fma2(o2[2 * j + 1], tk, p.y);
        }
    }

    float o[64];
    #pragma unroll
    for (int j = 0; j < 32; j++) {
        float2 f = unpack2(o2[j]);
        o[2 * j] = f.x; o[2 * j + 1] = f.y;
    }

    float s = 0.f, sq = 0.f;
    #pragma unroll
    for (int k = 0; k < 64; k++) { s += o[k]; sq += o[k] * o[k]; }
    float mu  = s * (1.f / 64.f);
    float var = sq * (1.f / 64.f) - mu * mu;
    float inv = rsqrtf(var + 1e-5f);

    float4* out4 = reinterpret_cast<float4*>(g_hn + (size_t)i * 64);
    __half2 h2[32];
    #pragma unroll
    for (int k4 = 0; k4 < 16; k4++) {
        float4 v;
        v.x = (o[4 * k4]     - mu) * inv * sg[4 * k4]     + sbb[4 * k4];
        v.y = (o[4 * k4 + 1] - mu) * inv * sg[4 * k4 + 1] + sbb[4 * k4 + 1];
        v.z = (o[4 * k4 + 2] - mu) * inv * sg[4 * k4 + 2] + sbb[4 * k4 + 2];
        v.w = (o[4 * k4 + 3] - mu) * inv * sg[4 * k4 + 3] + sbb[4 * k4 + 3];
        out4[k4] = v;
        h2[2 * k4]     = __floats2half2_rn(v.x, v.y);
        h2[2 * k4 + 1] = __floats2half2_rn(v.z, v.w);
    }
    uint4* d16 = reinterpret_cast<uint4*>(g_hn16 + (size_t)i * 64);
    const uint4* s16 = reinterpret_cast<const uint4*>(h2);
    #pragma unroll
    for (int q = 0; q < 8; q++) d16[q] = s16[q];
}

// ---------------------------------------------------------------------------
// CSR gather: msg[i] = sum_e w_e * hn16[src_e]. Warp per node.
// ---------------------------------------------------------------------------
__global__ void gather_kernel(int n) {
    const int lane = threadIdx.x & 31;
    int i = (blockIdx.x * blockDim.x + threadIdx.x) >> 5;
    if (i >= n) return;

    int deg = g_deg[i];
    if (deg > SLOT) deg = SLOT;
    const int4* row4 = reinterpret_cast<const int4*>(g_csr + (size_t)i * SLOT);
    const char* hb = reinterpret_cast<const char*>(g_hn16) + lane * 4;

    float ax = 0.f, ay = 0.f;
    int q = 0;
    for (; q + 4 <= deg; q += 4) {
        int4 a = row4[q >> 1];
        int4 b = row4[(q >> 1) + 1];
        __half2 v0 = *reinterpret_cast<const __half2*>(hb + a.x);
        __half2 v1 = *reinterpret_cast<const __half2*>(hb + a.z);
        __half2 v2 = *reinterpret_cast<const __half2*>(hb + b.x);
        __half2 v3 = *reinterpret_cast<const __half2*>(hb + b.z);
        float2 f0 = __half22float2(v0), f1 = __half22float2(v1);
        float2 f2 = __half22float2(v2), f3 = __half22float2(v3);
        float w0 = __int_as_float(a.y), w1 = __int_as_float(a.w);
        float w2 = __int_as_float(b.y), w3 = __int_as_float(b.w);
        ax += w0 * f0.x + w1 * f1.x + w2 * f2.x + w3 * f3.x;
        ay += w0 * f0.y + w1 * f1.y + w2 * f2.y + w3 * f3.y;
    }
    for (; q + 2 <= deg; q += 2) {
        int4 a = row4[q >> 1];
        __half2 v0 = *reinterpret_cast<const __half2*>(hb + a.x);
        __half2 v1 = *reinterpret_cast<const __half2*>(hb + a.z);
        float2 f0 = __half22float2(v0), f1 = __half22float2(v1);
        float w0 = __int_as_float(a.y), w1 = __int_as_float(a.w);
        ax += w0 * f0.x + w1 * f1.x;
        ay += w0 * f0.y + w1 * f1.y;
    }
    if (q < deg) {
        int2 e = reinterpret_cast<const int2*>(row4)[q];
        __half2 v = *reinterpret_cast<const __half2*>(hb + e.x);
        float2 f = __half22float2(v);
        float w = __int_as_float(e.y);
        ax += w * f.x;
        ay += w * f.y;
    }
    reinterpret_cast<float2*>(g_msg)[(size_t)i * 32 + lane] = make_float2(ax, ay);
}

// ---------------------------------------------------------------------------
// Half-node body: thread t of node i computes y[16t:16t+16] then, after a
// 1-lane shuffle exchange of z with its partner, o[32t:32t+32] (+residual).
// ---------------------------------------------------------------------------
__device__ __forceinline__ void half_node_body(
    int i, int t, const float* sNW, const float* sEW, const float* sMW,
    const float* sby, const float* smb, float (&o)[32]) {
    const float4* hn4 = reinterpret_cast<const float4*>(g_hn + (size_t)i * 64);
    const float4* m4  = reinterpret_cast<const float4*>(g_msg + (size_t)i * 64);

    // y-half accumulators: 16 outputs = 8 packed
    unsigned long long y2[8];
    const unsigned long long* sby2 =
        reinterpret_cast<const unsigned long long*>(sby) + 8 * t;
    #pragma unroll
    for (int j = 0; j < 8; j++) y2[j] = sby2[j];

    // y += hn @ nW[:, 16t:16t+16]
    #pragma unroll
    for (int k4 = 0; k4 < 16; k4++) {
        float4 hv = hn4[k4];
        float hc[4] = {hv.x, hv.y, hv.z, hv.w};
        #pragma unroll
        for (int c = 0; c < 4; c++) {
            unsigned long long hk = dup2(hc[c]);
            const ulonglong2* row =
                reinterpret_cast<const ulonglong2*>(sNW + (k4 * 4 + c) * 32 + 16 * t);
            #pragma unroll
            for (int j = 0; j < 4; j++) {
                ulonglong2 p = row[j];
                fma2(y2[2 * j],     hk, p.x);
                fma2(y2[2 * j + 1], hk, p.y);
            }
        }
    }

    // y += msg @ eW[:, 16t:16t+16]
    #pragma unroll
    for (int k4 = 0; k4 < 16; k4++) {
        float4 mv = m4[k4];
        float mc[4] = {mv.x, mv.y, mv.z, mv.w};
        #pragma unroll
        for (int c = 0; c < 4; c++) {
            unsigned long long mk = dup2(mc[c]);
            const ulonglong2* row =
                reinterpret_cast<const ulonglong2*>(sEW + (k4 * 4 + c) * 32 + 16 * t);
            #pragma unroll
            for (int j = 0; j < 4; j++) {
                ulonglong2 p = row[j];
                fma2(y2[2 * j],     mk, p.x);
                fma2(y2[2 * j + 1], mk, p.y);
            }
        }
    }

    float z[16];
    #pragma unroll
    for (int j = 0; j < 8; j++) {
        float2 f = unpack2(y2[j]);
        z[2 * j]     = lrelu(f.x);
        z[2 * j + 1] = lrelu(f.y);
    }

    // exchange z with partner (adjacent lane)
    float zo[16];
    #pragma unroll
    for (int q = 0; q < 16; q++) zo[q] = __shfl_xor_sync(FULLMASK, z[q], 1);

    // o[32t:32t+32] = zfull @ mW[:, 32t:32t+32] + mb-half
    unsigned long long o2[16];
    const unsigned long long* smb2 =
        reinterpret_cast<const unsigned long long*>(smb) + 16 * t;
    #pragma unroll
    for (int j = 0; j < 16; j++) o2[j] = smb2[j];

    #pragma unroll
    for (int k = 0; k < 32; k++) {
        float zv;
        if (k < 16) zv = t ? zo[k] : z[k];
        else        zv = t ? z[k - 16] : zo[k - 16];
        unsigned long long zk = dup2(zv);
        const ulonglong2* row =
            reinterpret_cast<const ulonglong2*>(sMW + k * 64 + 32 * t);
        #pragma unroll
        for (int j = 0; j < 8; j++) {
            ulonglong2 p = row[j];
            fma2(o2[2 * j],     zk, p.x);
            fma2(o2[2 * j + 1], zk, p.y);
        }
    }

    #pragma unroll
    for (int j = 0; j < 16; j++) {
        float2 f = unpack2(o2[j]);
        o[2 * j] = f.x; o[2 * j + 1] = f.y;
    }
    // residual (own 32 channels)
    const float4* hnh = reinterpret_cast<const float4*>(g_hn + (size_t)i * 64 + 32 * t);
    #pragma unroll
    for (int k4 = 0; k4 < 8; k4++) {
        float4 hv = hnh[k4];
        o[4 * k4]     += hv.x;
        o[4 * k4 + 1] += hv.y;
        o[4 * k4 + 2] += hv.z;
        o[4 * k4 + 3] += hv.w;
    }
}

// ---------------------------------------------------------------------------
// Layers 0-2: half-node update + pairwise LN -> writes g_hn / g_hn16 in place
// ---------------------------------------------------------------------------
__global__ void __launch_bounds__(128, 4)
update_kernel(const float* __restrict__ nW, const float* __restrict__ nb,
              const float* __restrict__ eW, const float* __restrict__ eb,
              const float* __restrict__ mW, const float* __restrict__ mb,
              const float* __restrict__ lg, const float* __restrict__ lb, int n) {
    __shared__ __align__(16) float sNW[64 * 32];
    __shared__ __align__(16) float sEW[64 * 32];
    __shared__ __align__(16) float sMW[32 * 64];
    __shared__ __align__(16) float sby[32];
    __shared__ __align__(16) float smb[64];
    __shared__ float sg[64], sbb[64];
    for (int i = threadIdx.x; i < 2048; i += 128) {
        sNW[i] = nW[i];
        sEW[i] = eW[i];
        sMW[i] = mW[i];
    }
    if (threadIdx.x < 32) sby[threadIdx.x] = nb[threadIdx.x] + eb[threadIdx.x];
    if (threadIdx.x < 64) {
        smb[threadIdx.x] = mb[threadIdx.x];
        sg[threadIdx.x]  = lg[threadIdx.x];
        sbb[threadIdx.x] = lb[threadIdx.x];
    }
    __syncthreads();

    int tid = blockIdx.x * 128 + threadIdx.x;
    int i = tid >> 1;
    int t = tid & 1;
    if (i >= n) return;

    float o[32];
    half_node_body(i, t, sNW, sEW, sMW, sby, smb, o);

    // LN: partial stats over own 32 channels + pair reduce
    float s = 0.f, sq = 0.f;
    #pragma unroll
    for (int k = 0; k < 32; k++) { s += o[k]; sq += o[k] * o[k]; }
    s  += __shfl_xor_sync(FULLMASK, s, 1);
    sq += __shfl_xor_sync(FULLMASK, sq, 1);
    float mu  = s * (1.f / 64.f);
    float var = sq * (1.f / 64.f) - mu * mu;
    float inv = rsqrtf(var + 1e-5f);

    const int cb = 32 * t;  // channel base
    float4* out4 = reinterpret_cast<float4*>(g_hn + (size_t)i * 64 + cb);
    __half2 h2[16];
    #pragma unroll
    for (int k4 = 0; k4 < 8; k4++) {
        float4 v;
        v.x = (o[4 * k4]     - mu) * inv * sg[cb + 4 * k4]     + sbb[cb + 4 * k4];
        v.y = (o[4 * k4 + 1] - mu) * inv * sg[cb + 4 * k4 + 1] + sbb[cb + 4 * k4 + 1];
        v.z = (o[4 * k4 + 2] - mu) * inv * sg[cb + 4 * k4 + 2] + sbb[cb + 4 * k4 + 2];
        v.w = (o[4 * k4 + 3] - mu) * inv * sg[cb + 4 * k4 + 3] + sbb[cb + 4 * k4 + 3];
        out4[k4] = v;
        h2[2 * k4]     = __floats2half2_rn(v.x, v.y);
        h2[2 * k4 + 1] = __floats2half2_rn(v.z, v.w);
    }
    uint4* d16 = reinterpret_cast<uint4*>(g_hn16 + (size_t)i * 64 + cb);
    const uint4* s16 = reinterpret_cast<const uint4*>(h2);
    #pragma unroll
    for (int q = 0; q < 4; q++) d16[q] = s16[q];
}

// ---------------------------------------------------------------------------
// Layer 3 + decoder, half-node per thread.
// ---------------------------------------------------------------------------
__global__ void __launch_bounds__(128, 4)
update_dec_kernel(const float* __restrict__ nW, const float* __restrict__ nb,
                  const float* __restrict__ eW, const float* __restrict__ eb,
                  const float* __restrict__ mW, const float* __restrict__ mb,
                  const float* __restrict__ dW1, const float* __restrict__ db1,
                  const float* __restrict__ dW2, const float* __restrict__ db2,
                  float* __restrict__ out, int n) {
    __shared__ __align__(16) float sNW[64 * 32];
    __shared__ __align__(16) float sEW[64 * 32];
    __shared__ __align__(16) float sMW[32 * 64];
    __shared__ __align__(16) float sby[32];
    __shared__ __align__(16) float smb[64];
    __shared__ __align__(16) float sW1T[24 * 64];  // [j][k] = dW1[k][j]
    __shared__ float sW2T[3 * 24];
    __shared__ float sdb1[24];
    __shared__ float sdb2[3];
    for (int i = threadIdx.x; i < 2048; i += 128) {
        sNW[i] = nW[i];
        sEW[i] = eW[i];
        sMW[i] = mW[i];
    }
    for (int i = threadIdx.x; i < 1536; i += 128) {
        int k = i / 24, j = i % 24;
        sW1T[j * 64 + k] = dW1[i];
    }
    if (threadIdx.x < 72) {
        int j = threadIdx.x / 3, c = threadIdx.x % 3;
        sW2T[c * 24 + j] = dW2[threadIdx.x];
    }
    if (threadIdx.x < 32) sby[threadIdx.x] = nb[threadIdx.x] + eb[threadIdx.x];
    if (threadIdx.x < 64) smb[threadIdx.x] = mb[threadIdx.x];
    if (threadIdx.x < 24) sdb1[threadIdx.x] = db1[threadIdx.x];
    if (threadIdx.x < 3)  sdb2[threadIdx.x] = db2[threadIdx.x];
    __syncthreads();

    int tid = blockIdx.x * 128 + threadIdx.x;
    int i = tid >> 1;
    int t = tid & 1;
    if (i >= n) return;

    float o[32];
    half_node_body(i, t, sNW, sEW, sMW, sby, smb, o);

    // decoder stage 1: tfull[j] = leaky(db1[j] + o_full . dW1[:,j]) via partials
    unsigned long long op[16];
    #pragma unroll
    for (int q = 0; q < 16; q++) op[q] = pack2(o[2 * q], o[2 * q + 1]);

    float tf[24];
    #pragma unroll
    for (int j = 0; j < 24; j++) {
        unsigned long long acc = 0ULL;
        const ulonglong2* row =
            reinterpret_cast<const ulonglong2*>(sW1T + j * 64 + 32 * t);
        #pragma unroll
        for (int m = 0; m < 8; m++) {
            ulonglong2 p = row[m];
            fma2(acc, op[2 * m],     p.x);
            fma2(acc, op[2 * m + 1], p.y);
        }
        float2 f = unpack2(acc);
        float part = f.x + f.y;
        part += __shfl_xor_sync(FULLMASK, part, 1);
        tf[j] = lrelu(sdb1[j] + part);
    }

    // decoder stage 2: 3 outputs, written by t==0
    if (t == 0) {
        #pragma unroll
        for (int c = 0; c < 3; c++) {
            float oo = sdb2[c];
            #pragma unroll
            for (int j = 0; j < 24; j++) oo += tf[j] * sW2T[c * 24 + j];
            out[(size_t)i * 3 + c] = oo;
        }
    }
}

// ---------------------------------------------------------------------------
extern "C" void kernel_launch(void* const* d_in, const int* in_sizes, int n_in,
                              void* d_out, int out_size) {
    const float* x       = (const float*)d_in[0];
    // d_in[1] = pos (unused by reference)
    const int*   esrc    = (const int*)  d_in[2];
    const int*   edst    = (const int*)  d_in[3];
    const float* ew      = (const float*)d_in[4];
    const float* enc_W1  = (const float*)d_in[5];
    const float* enc_b1  = (const float*)d_in[6];
    const float* enc_W2  = (const float*)d_in[7];
    const float* enc_b2  = (const float*)d_in[8];
    const float* dec_W1  = (const float*)d_in[9];
    const float* dec_b1  = (const float*)d_in[10];
    const float* dec_W2  = (const float*)d_in[11];
    const float* dec_b2  = (const float*)d_in[12];
    const float* ln_g    = (const float*)d_in[13];
    const float* ln_b    = (const float*)d_in[14];
    const float* node_W  = (const float*)d_in[15];
    const float* node_b  = (const float*)d_in[16];
    const float* edge_W  = (const float*)d_in[17];
    const float* edge_b  = (const float*)d_in[18];
    const float* mlp_W   = (const float*)d_in[19];
    const float* mlp_b   = (const float*)d_in[20];

    const int n  = in_sizes[0] / 16;   // 100000 nodes
    const int ne = in_sizes[2];        // 1200000 edges

    const int nb  = (n + 255) / 256;
    const int fe  = (ne + 255) / 256;
    const int ga  = (int)(((long long)n * 32 + 255) / 256);
    const int ub  = (2 * n + 127) / 128;   // half-node threads, 128/block

    // enc zeroes g_deg; fill must follow enc
    enc_kernel<<<nb, 256>>>(x, enc_W1, enc_b1, enc_W2, enc_b2, ln_g, ln_b, n);
    fill_csr_kernel<<<fe, 256>>>(esrc, edst, ew, ne);

    for (int l = 0; l < 3; l++) {
        gather_kernel<<<ga, 256>>>(n);
        update_kernel<<<ub, 128>>>(node_W + l * 2048, node_b + l * 32,
                                   edge_W + l * 2048, edge_b + l * 32,
                                   mlp_W  + l * 2048, mlp_b  + l * 64,
                                   ln_g + (l + 1) * 64, ln_b + (l + 1) * 64, n);
    }

    gather_kernel<<<ga, 256>>>(n);
    update_dec_kernel<<<ub, 128>>>(node_W + 3 * 2048, node_b + 3 * 32,
                                   edge_W + 3 * 2048, edge_b + 3 * 32,
                                   mlp_W  + 3 * 2048, mlp_b  + 3 * 64,
                                   dec_W1, dec_b1, dec_W2, dec_b2,
                                   (float*)d_out, n);
}

// round 7
// speedup vs baseline: 1.0973x; 1.0973x over previous
#include <cuda_runtime.h>
#include <cuda_fp16.h>

#define NMAX 100000
#define SLOT 64
#define FULLMASK 0xffffffffu

// Scratch (allocation-free)
__device__ float g_hn[NMAX * 64];                    // LN'd state fp32
__device__ __align__(16) __half g_hn16[NMAX * 64];   // LN'd state fp16 (gather operand)
__device__ float g_msg[NMAX * 64];                   // gathered messages
__device__ int  g_deg[NMAX];
__device__ int2 g_csr[(size_t)NMAX * SLOT];          // (src byte offset, w bits)

// Packed per-layer weights (device staging) -> copied into __constant__ per layer
#define LPACK 6368
__device__ __align__(16) float g_packL[4 * LPACK];
__device__ __align__(16) float g_packD[1636];

// Constant banks: per-layer weights + decoder weights
__constant__ __align__(16) float cL[LPACK];
__constant__ __align__(16) float cD[1636];

// cL layout
#define C_NW 0        // 64x32
#define C_EW 2048     // 64x32
#define C_MW 4096     // 32x64
#define C_BY 6144     // nb+eb (32)
#define C_MB 6176     // 64
#define C_G  6240     // next-layer LN gamma (64)
#define C_B  6304     // next-layer LN beta (64)
// cD layout: dW1T [24][64] at 0, dW2T [3][24] at 1536, db1 at 1608, db2 at 1632

__device__ __forceinline__ float lrelu(float v) { return v >= 0.f ? v : 0.01f * v; }

// ---- packed f32x2 helpers (sm_103a) ---------------------------------------
__device__ __forceinline__ unsigned long long dup2(float v) {
    unsigned long long r;
    asm("mov.b64 %0, {%1, %1};" : "=l"(r) : "f"(v));
    return r;
}
__device__ __forceinline__ unsigned long long pack2(float a, float b) {
    unsigned long long r;
    asm("mov.b64 %0, {%1, %2};" : "=l"(r) : "f"(a), "f"(b));
    return r;
}
__device__ __forceinline__ void fma2(unsigned long long& acc, unsigned long long a,
                                     unsigned long long b) {
    asm("fma.rn.f32x2 %0, %1, %2, %0;" : "+l"(acc) : "l"(a), "l"(b));
}
__device__ __forceinline__ float2 unpack2(unsigned long long v) {
    float2 f;
    asm("mov.b64 {%0, %1}, %2;" : "=f"(f.x), "=f"(f.y) : "l"(v));
    return f;
}

// ---------------------------------------------------------------------------
// Pack weights for constant-bank staging
// ---------------------------------------------------------------------------
__global__ void pack_kernel(const float* __restrict__ nW, const float* __restrict__ nb,
                            const float* __restrict__ eW, const float* __restrict__ eb,
                            const float* __restrict__ mW, const float* __restrict__ mb,
                            const float* __restrict__ lg, const float* __restrict__ lb,
                            const float* __restrict__ dW1, const float* __restrict__ db1,
                            const float* __restrict__ dW2, const float* __restrict__ db2) {
    int i = blockIdx.x * 256 + threadIdx.x;
    if (i < 4 * LPACK) {
        int l = i / LPACK, r = i % LPACK;
        float v;
        if (r < 2048)      v = nW[l * 2048 + r];
        else if (r < 4096) v = eW[l * 2048 + r - 2048];
        else if (r < 6144) v = mW[l * 2048 + r - 4096];
        else if (r < 6176) v = nb[l * 32 + r - 6144] + eb[l * 32 + r - 6144];
        else if (r < 6240) v = mb[l * 64 + r - 6176];
        else if (r < 6304) v = (l < 3) ? lg[(l + 1) * 64 + (r - 6240)] : 1.f;
        else               v = (l < 3) ? lb[(l + 1) * 64 + (r - 6304)] : 0.f;
        g_packL[i] = v;
    } else if (i < 4 * LPACK + 1636) {
        int r = i - 4 * LPACK;
        float v = 0.f;
        if (r < 1536) { int j = r / 64, k = r % 64; v = dW1[k * 24 + j]; }
        else if (r < 1608) { int q = r - 1536; int c = q / 24, j = q % 24; v = dW2[j * 3 + c]; }
        else if (r < 1632) v = db1[r - 1608];
        else if (r < 1635) v = db2[r - 1632];
        g_packD[r] = v;
    }
}

// ---------------------------------------------------------------------------
// CSR fill (g_deg zeroed by enc_kernel, which runs first)
// ---------------------------------------------------------------------------
__global__ void fill_csr_kernel(const int* __restrict__ src, const int* __restrict__ dst,
                                const float* __restrict__ w, int ne) {
    int e = blockIdx.x * blockDim.x + threadIdx.x;
    if (e >= ne) return;
    int d = dst[e];
    int slot = atomicAdd(&g_deg[d], 1);
    if (slot < SLOT)
        g_csr[(size_t)d * SLOT + slot] = make_int2(src[e] * 128, __float_as_int(w[e]));
}

// ---------------------------------------------------------------------------
// Encoder + LN(layer 0), THREAD per node (smem weights). Zeroes g_deg.
// ---------------------------------------------------------------------------
__global__ void __launch_bounds__(256, 2)
enc_kernel(const float* __restrict__ x,
           const float* __restrict__ W1, const float* __restrict__ b1,
           const float* __restrict__ W2, const float* __restrict__ b2,
           const float* __restrict__ lg, const float* __restrict__ lb, int n) {
    __shared__ __align__(16) float sW1T[128 * 16];  // [k][j] = W1[j][k]
    __shared__ __align__(16) float sW2[128 * 64];
    __shared__ float sb1[128];
    __shared__ __align__(16) float sb2[64];
    __shared__ float sg[64], sbb[64];
    for (int i = threadIdx.x; i < 2048; i += 256) {
        int j = i >> 7, k = i & 127;
        sW1T[k * 16 + j] = W1[i];
    }
    for (int i = threadIdx.x; i < 8192; i += 256) sW2[i] = W2[i];
    if (threadIdx.x < 128) sb1[threadIdx.x] = b1[threadIdx.x];
    if (threadIdx.x < 64) {
        sb2[threadIdx.x] = b2[threadIdx.x];
        sg[threadIdx.x]  = lg[threadIdx.x];
        sbb[threadIdx.x] = lb[threadIdx.x];
    }
    __syncthreads();

    int i = blockIdx.x * 256 + threadIdx.x;
    if (i >= n) return;
    g_deg[i] = 0;   // prepare for fill_csr_kernel

    float xr[16];
    const float4* xp = reinterpret_cast<const float4*>(x + (size_t)i * 16);
    #pragma unroll
    for (int q = 0; q < 4; q++) {
        float4 v = xp[q];
        xr[4 * q] = v.x; xr[4 * q + 1] = v.y; xr[4 * q + 2] = v.z; xr[4 * q + 3] = v.w;
    }

    unsigned long long o2[32];
    const unsigned long long* sb2p = reinterpret_cast<const unsigned long long*>(sb2);
    #pragma unroll
    for (int j = 0; j < 32; j++) o2[j] = sb2p[j];

    #pragma unroll 8
    for (int k = 0; k < 128; k++) {
        const float4* c = reinterpret_cast<const float4*>(sW1T + k * 16);
        float t = sb1[k];
        #pragma unroll
        for (int q = 0; q < 4; q++) {
            float4 wv = c[q];
            t += wv.x * xr[4 * q] + wv.y * xr[4 * q + 1]
               + wv.z * xr[4 * q + 2] + wv.w * xr[4 * q + 3];
        }
        t = lrelu(t);
        unsigned long long tk = dup2(t);
        const ulonglong2* row = reinterpret_cast<const ulonglong2*>(sW2 + k * 64);
        #pragma unroll
        for (int j = 0; j < 16; j++) {
            ulonglong2 p = row[j];
            fma2(o2[2 * j],     tk, p.x);
            fma2(o2[2 * j + 1], tk, p.y);
        }
    }

    float o[64];
    #pragma unroll
    for (int j = 0; j < 32; j++) {
        float2 f = unpack2(o2[j]);
        o[2 * j] = f.x; o[2 * j + 1] = f.y;
    }

    float s = 0.f, sq = 0.f;
    #pragma unroll
    for (int k = 0; k < 64; k++) { s += o[k]; sq += o[k] * o[k]; }
    float mu  = s * (1.f / 64.f);
    float var = sq * (1.f / 64.f) - mu * mu;
    float inv = rsqrtf(var + 1e-5f);

    float4* out4 = reinterpret_cast<float4*>(g_hn + (size_t)i * 64);
    __half2 h2[32];
    #pragma unroll
    for (int k4 = 0; k4 < 16; k4++) {
        float4 v;
        v.x = (o[4 * k4]     - mu) * inv * sg[4 * k4]     + sbb[4 * k4];
        v.y = (o[4 * k4 + 1] - mu) * inv * sg[4 * k4 + 1] + sbb[4 * k4 + 1];
        v.z = (o[4 * k4 + 2] - mu) * inv * sg[4 * k4 + 2] + sbb[4 * k4 + 2];
        v.w = (o[4 * k4 + 3] - mu) * inv * sg[4 * k4 + 3] + sbb[4 * k4 + 3];
        out4[k4] = v;
        h2[2 * k4]     = __floats2half2_rn(v.x, v.y);
        h2[2 * k4 + 1] = __floats2half2_rn(v.z, v.w);
    }
    uint4* d16 = reinterpret_cast<uint4*>(g_hn16 + (size_t)i * 64);
    const uint4* s16 = reinterpret_cast<const uint4*>(h2);
    #pragma unroll
    for (int q = 0; q < 8; q++) d16[q] = s16[q];
}

// ---------------------------------------------------------------------------
// CSR gather: msg[i] = sum_e w_e * hn16[src_e]. Warp per node.
// ---------------------------------------------------------------------------
__global__ void gather_kernel(int n) {
    const int lane = threadIdx.x & 31;
    int i = (blockIdx.x * blockDim.x + threadIdx.x) >> 5;
    if (i >= n) return;

    int deg = g_deg[i];
    if (deg > SLOT) deg = SLOT;
    const int4* row4 = reinterpret_cast<const int4*>(g_csr + (size_t)i * SLOT);
    const char* hb = reinterpret_cast<const char*>(g_hn16) + lane * 4;

    float ax = 0.f, ay = 0.f;
    int q = 0;
    for (; q + 4 <= deg; q += 4) {
        int4 a = row4[q >> 1];
        int4 b = row4[(q >> 1) + 1];
        __half2 v0 = *reinterpret_cast<const __half2*>(hb + a.x);
        __half2 v1 = *reinterpret_cast<const __half2*>(hb + a.z);
        __half2 v2 = *reinterpret_cast<const __half2*>(hb + b.x);
        __half2 v3 = *reinterpret_cast<const __half2*>(hb + b.z);
        float2 f0 = __half22float2(v0), f1 = __half22float2(v1);
        float2 f2 = __half22float2(v2), f3 = __half22float2(v3);
        float w0 = __int_as_float(a.y), w1 = __int_as_float(a.w);
        float w2 = __int_as_float(b.y), w3 = __int_as_float(b.w);
        ax += w0 * f0.x + w1 * f1.x + w2 * f2.x + w3 * f3.x;
        ay += w0 * f0.y + w1 * f1.y + w2 * f2.y + w3 * f3.y;
    }
    for (; q + 2 <= deg; q += 2) {
        int4 a = row4[q >> 1];
        __half2 v0 = *reinterpret_cast<const __half2*>(hb + a.x);
        __half2 v1 = *reinterpret_cast<const __half2*>(hb + a.z);
        float2 f0 = __half22float2(v0), f1 = __half22float2(v1);
        float w0 = __int_as_float(a.y), w1 = __int_as_float(a.w);
        ax += w0 * f0.x + w1 * f1.x;
        ay += w0 * f0.y + w1 * f1.y;
    }
    if (q < deg) {
        int2 e = reinterpret_cast<const int2*>(row4)[q];
        __half2 v = *reinterpret_cast<const __half2*>(hb + e.x);
        float2 f = __half22float2(v);
        float w = __int_as_float(e.y);
        ax += w * f.x;
        ay += w * f.y;
    }
    reinterpret_cast<float2*>(g_msg)[(size_t)i * 32 + lane] = make_float2(ax, ay);
}

// ---------------------------------------------------------------------------
// Node body with CONSTANT-BANK weights: y = hn@nW + msg@eW + by;
// o = leaky(y)@mW + mb + hn   (o left in registers)
// ---------------------------------------------------------------------------
__device__ __forceinline__ void node_body_const(int i, float (&o)[64]) {
    const float4* hn4 = reinterpret_cast<const float4*>(g_hn + (size_t)i * 64);
    const float4* m4  = reinterpret_cast<const float4*>(g_msg + (size_t)i * 64);

    unsigned long long y2[16];
    #pragma unroll
    for (int j = 0; j < 16; j++)
        y2[j] = *reinterpret_cast<const unsigned long long*>(&cL[C_BY + 2 * j]);

    // y += hn @ nW
    #pragma unroll
    for (int k4 = 0; k4 < 16; k4++) {
        float4 hv = hn4[k4];
        float hc[4] = {hv.x, hv.y, hv.z, hv.w};
        #pragma unroll
        for (int c = 0; c < 4; c++) {
            unsigned long long hk = dup2(hc[c]);
            #pragma unroll
            for (int j = 0; j < 8; j++) {
                ulonglong2 p = *reinterpret_cast<const ulonglong2*>(
                    &cL[C_NW + (k4 * 4 + c) * 32 + 4 * j]);
                fma2(y2[2 * j],     hk, p.x);
                fma2(y2[2 * j + 1], hk, p.y);
            }
        }
    }

    // y += msg @ eW
    #pragma unroll
    for (int k4 = 0; k4 < 16; k4++) {
        float4 mv = m4[k4];
        float mc[4] = {mv.x, mv.y, mv.z, mv.w};
        #pragma unroll
        for (int c = 0; c < 4; c++) {
            unsigned long long mk = dup2(mc[c]);
            #pragma unroll
            for (int j = 0; j < 8; j++) {
                ulonglong2 p = *reinterpret_cast<const ulonglong2*>(
                    &cL[C_EW + (k4 * 4 + c) * 32 + 4 * j]);
                fma2(y2[2 * j],     mk, p.x);
                fma2(y2[2 * j + 1], mk, p.y);
            }
        }
    }

    float z[32];
    #pragma unroll
    for (int j = 0; j < 16; j++) {
        float2 f = unpack2(y2[j]);
        z[2 * j]     = lrelu(f.x);
        z[2 * j + 1] = lrelu(f.y);
    }

    unsigned long long o2[32];
    #pragma unroll
    for (int j = 0; j < 32; j++)
        o2[j] = *reinterpret_cast<const unsigned long long*>(&cL[C_MB + 2 * j]);

    #pragma unroll
    for (int k = 0; k < 32; k++) {
        unsigned long long zk = dup2(z[k]);
        #pragma unroll
        for (int j = 0; j < 16; j++) {
            ulonglong2 p = *reinterpret_cast<const ulonglong2*>(
                &cL[C_MW + k * 64 + 4 * j]);
            fma2(o2[2 * j],     zk, p.x);
            fma2(o2[2 * j + 1], zk, p.y);
        }
    }

    #pragma unroll
    for (int j = 0; j < 32; j++) {
        float2 f = unpack2(o2[j]);
        o[2 * j] = f.x; o[2 * j + 1] = f.y;
    }
    #pragma unroll
    for (int k4 = 0; k4 < 16; k4++) {
        float4 hv = hn4[k4];
        o[4 * k4]     += hv.x;
        o[4 * k4 + 1] += hv.y;
        o[4 * k4 + 2] += hv.z;
        o[4 * k4 + 3] += hv.w;
    }
}

// ---------------------------------------------------------------------------
// Layers 0-2: update + LN (gamma/beta from cL), writes g_hn/g_hn16 in place
// ---------------------------------------------------------------------------
__global__ void __launch_bounds__(256)
update_kernel(int n) {
    int i = blockIdx.x * 256 + threadIdx.x;
    if (i >= n) return;

    float o[64];
    node_body_const(i, o);

    float s = 0.f, sq = 0.f;
    #pragma unroll
    for (int k = 0; k < 64; k++) { s += o[k]; sq += o[k] * o[k]; }
    float mu  = s * (1.f / 64.f);
    float var = sq * (1.f / 64.f) - mu * mu;
    float inv = rsqrtf(var + 1e-5f);

    float4* out4 = reinterpret_cast<float4*>(g_hn + (size_t)i * 64);
    __half2 h2[32];
    #pragma unroll
    for (int k4 = 0; k4 < 16; k4++) {
        float4 v;
        v.x = (o[4 * k4]     - mu) * inv * cL[C_G + 4 * k4]     + cL[C_B + 4 * k4];
        v.y = (o[4 * k4 + 1] - mu) * inv * cL[C_G + 4 * k4 + 1] + cL[C_B + 4 * k4 + 1];
        v.z = (o[4 * k4 + 2] - mu) * inv * cL[C_G + 4 * k4 + 2] + cL[C_B + 4 * k4 + 2];
        v.w = (o[4 * k4 + 3] - mu) * inv * cL[C_G + 4 * k4 + 3] + cL[C_B + 4 * k4 + 3];
        out4[k4] = v;
        h2[2 * k4]     = __floats2half2_rn(v.x, v.y);
        h2[2 * k4 + 1] = __floats2half2_rn(v.z, v.w);
    }
    uint4* d16 = reinterpret_cast<uint4*>(g_hn16 + (size_t)i * 64);
    const uint4* s16 = reinterpret_cast<const uint4*>(h2);
    #pragma unroll
    for (int q = 0; q < 8; q++) d16[q] = s16[q];
}

// ---------------------------------------------------------------------------
// Layer 3 + decoder (decoder weights from cD)
// ---------------------------------------------------------------------------
__global__ void __launch_bounds__(256)
update_dec_kernel(float* __restrict__ out, int n) {
    int i = blockIdx.x * 256 + threadIdx.x;
    if (i >= n) return;

    float o[64];
    node_body_const(i, o);

    unsigned long long hp[32];
    #pragma unroll
    for (int q = 0; q < 32; q++) hp[q] = pack2(o[2 * q], o[2 * q + 1]);

    float t[24];
    #pragma unroll
    for (int j = 0; j < 24; j++) {
        unsigned long long acc = 0ULL;
        #pragma unroll
        for (int m = 0; m < 16; m++) {
            ulonglong2 p = *reinterpret_cast<const ulonglong2*>(&cD[j * 64 + 4 * m]);
            fma2(acc, hp[2 * m],     p.x);
            fma2(acc, hp[2 * m + 1], p.y);
        }
        float2 f = unpack2(acc);
        t[j] = lrelu(cD[1608 + j] + f.x + f.y);
    }

    #pragma unroll
    for (int c = 0; c < 3; c++) {
        float oo = cD[1632 + c];
        #pragma unroll
        for (int j = 0; j < 24; j++) oo += t[j] * cD[1536 + c * 24 + j];
        out[(size_t)i * 3 + c] = oo;
    }
}

// ---------------------------------------------------------------------------
extern "C" void kernel_launch(void* const* d_in, const int* in_sizes, int n_in,
                              void* d_out, int out_size) {
    const float* x       = (const float*)d_in[0];
    // d_in[1] = pos (unused by reference)
    const int*   esrc    = (const int*)  d_in[2];
    const int*   edst    = (const int*)  d_in[3];
    const float* ew      = (const float*)d_in[4];
    const float* enc_W1  = (const float*)d_in[5];
    const float* enc_b1  = (const float*)d_in[6];
    const float* enc_W2  = (const float*)d_in[7];
    const float* enc_b2  = (const float*)d_in[8];
    const float* dec_W1  = (const float*)d_in[9];
    const float* dec_b1  = (const float*)d_in[10];
    const float* dec_W2  = (const float*)d_in[11];
    const float* dec_b2  = (const float*)d_in[12];
    const float* ln_g    = (const float*)d_in[13];
    const float* ln_b    = (const float*)d_in[14];
    const float* node_W  = (const float*)d_in[15];
    const float* node_b  = (const float*)d_in[16];
    const float* edge_W  = (const float*)d_in[17];
    const float* edge_b  = (const float*)d_in[18];
    const float* mlp_W   = (const float*)d_in[19];
    const float* mlp_b   = (const float*)d_in[20];

    const int n  = in_sizes[0] / 16;   // 100000 nodes
    const int ne = in_sizes[2];        // 1200000 edges

    const int nb = (n + 255) / 256;
    const int fe = (ne + 255) / 256;
    const int ga = (int)(((long long)n * 32 + 255) / 256);
    const int pk = (4 * LPACK + 1636 + 255) / 256;

    float* packL = nullptr;
    cudaGetSymbolAddress((void**)&packL, g_packL);
    float* packD = nullptr;
    cudaGetSymbolAddress((void**)&packD, g_packD);

    // pack weights, run encoder (also zeroes g_deg), build CSR
    pack_kernel<<<pk, 256>>>(node_W, node_b, edge_W, edge_b, mlp_W, mlp_b,
                             ln_g, ln_b, dec_W1, dec_b1, dec_W2, dec_b2);
    enc_kernel<<<nb, 256>>>(x, enc_W1, enc_b1, enc_W2, enc_b2, ln_g, ln_b, n);
    fill_csr_kernel<<<fe, 256>>>(esrc, edst, ew, ne);

    // decoder constants (used only by the last kernel)
    cudaMemcpyToSymbolAsync(cD, packD, 1636 * sizeof(float), 0,
                            cudaMemcpyDeviceToDevice, 0);

    for (int l = 0; l < 3; l++) {
        cudaMemcpyToSymbolAsync(cL, packL + (size_t)l * LPACK, LPACK * sizeof(float),
                                0, cudaMemcpyDeviceToDevice, 0);
        gather_kernel<<<ga, 256>>>(n);
        update_kernel<<<nb, 256>>>(n);
    }

    cudaMemcpyToSymbolAsync(cL, packL + (size_t)3 * LPACK, LPACK * sizeof(float),
                            0, cudaMemcpyDeviceToDevice, 0);
    gather_kernel<<<ga, 256>>>(n);
    update_dec_kernel<<<nb, 256>>>((float*)d_out, n);
}

// round 8
// speedup vs baseline: 1.1975x; 1.0913x over previous
#include <cuda_runtime.h>
#include <cuda_fp16.h>

#define NMAX 100000
#define SLOT 64
#define FULLMASK 0xffffffffu

// Scratch (allocation-free)
__device__ float g_hn[NMAX * 64];                    // LN'd state fp32 (gather + update input)
__device__ float g_msg[NMAX * 64];                   // gathered messages
__device__ int  g_deg[NMAX];
__device__ int2 g_csr[(size_t)NMAX * SLOT];          // (src byte offset = src*256, w bits)

// Packed per-layer weights (device staging) -> copied into __constant__ per layer
#define LPACK 6368
__device__ __align__(16) float g_packL[4 * LPACK];
__device__ __align__(16) float g_packD[1636];

// Constant banks: per-layer weights + decoder weights
__constant__ __align__(16) float cL[LPACK];
__constant__ __align__(16) float cD[1636];

// cL layout
#define C_NW 0        // 64x32
#define C_EW 2048     // 64x32
#define C_MW 4096     // 32x64
#define C_BY 6144     // nb+eb (32)
#define C_MB 6176     // 64
#define C_G  6240     // next-layer LN gamma (64)
#define C_B  6304     // next-layer LN beta (64)
// cD layout: dW1T [24][64] at 0, dW2T [3][24] at 1536, db1 at 1608, db2 at 1632

__device__ __forceinline__ float lrelu(float v) { return v >= 0.f ? v : 0.01f * v; }

// ---- packed f32x2 helpers (sm_103a) ---------------------------------------
__device__ __forceinline__ unsigned long long dup2(float v) {
    unsigned long long r;
    asm("mov.b64 %0, {%1, %1};" : "=l"(r) : "f"(v));
    return r;
}
__device__ __forceinline__ unsigned long long pack2(float a, float b) {
    unsigned long long r;
    asm("mov.b64 %0, {%1, %2};" : "=l"(r) : "f"(a), "f"(b));
    return r;
}
__device__ __forceinline__ void fma2(unsigned long long& acc, unsigned long long a,
                                     unsigned long long b) {
    asm("fma.rn.f32x2 %0, %1, %2, %0;" : "+l"(acc) : "l"(a), "l"(b));
}
__device__ __forceinline__ float2 unpack2(unsigned long long v) {
    float2 f;
    asm("mov.b64 {%0, %1}, %2;" : "=f"(f.x), "=f"(f.y) : "l"(v));
    return f;
}

// ---------------------------------------------------------------------------
// Pack weights for constant-bank staging
// ---------------------------------------------------------------------------
__global__ void pack_kernel(const float* __restrict__ nW, const float* __restrict__ nb,
                            const float* __restrict__ eW, const float* __restrict__ eb,
                            const float* __restrict__ mW, const float* __restrict__ mb,
                            const float* __restrict__ lg, const float* __restrict__ lb,
                            const float* __restrict__ dW1, const float* __restrict__ db1,
                            const float* __restrict__ dW2, const float* __restrict__ db2) {
    int i = blockIdx.x * 256 + threadIdx.x;
    if (i < 4 * LPACK) {
        int l = i / LPACK, r = i % LPACK;
        float v;
        if (r < 2048)      v = nW[l * 2048 + r];
        else if (r < 4096) v = eW[l * 2048 + r - 2048];
        else if (r < 6144) v = mW[l * 2048 + r - 4096];
        else if (r < 6176) v = nb[l * 32 + r - 6144] + eb[l * 32 + r - 6144];
        else if (r < 6240) v = mb[l * 64 + r - 6176];
        else if (r < 6304) v = (l < 3) ? lg[(l + 1) * 64 + (r - 6240)] : 1.f;
        else               v = (l < 3) ? lb[(l + 1) * 64 + (r - 6304)] : 0.f;
        g_packL[i] = v;
    } else if (i < 4 * LPACK + 1636) {
        int r = i - 4 * LPACK;
        float v = 0.f;
        if (r < 1536) { int j = r / 64, k = r % 64; v = dW1[k * 24 + j]; }
        else if (r < 1608) { int q = r - 1536; int c = q / 24, j = q % 24; v = dW2[j * 3 + c]; }
        else if (r < 1632) v = db1[r - 1608];
        else if (r < 1635) v = db2[r - 1632];
        g_packD[r] = v;
    }
}

// ---------------------------------------------------------------------------
// CSR fill (g_deg zeroed by enc_kernel, which runs first)
// ---------------------------------------------------------------------------
__global__ void fill_csr_kernel(const int* __restrict__ src, const int* __restrict__ dst,
                                const float* __restrict__ w, int ne) {
    int e = blockIdx.x * blockDim.x + threadIdx.x;
    if (e >= ne) return;
    int d = dst[e];
    int slot = atomicAdd(&g_deg[d], 1);
    if (slot < SLOT)
        g_csr[(size_t)d * SLOT + slot] = make_int2(src[e] * 256, __float_as_int(w[e]));
}

// ---------------------------------------------------------------------------
// Encoder + LN(layer 0), THREAD per node (smem weights). Zeroes g_deg.
// ---------------------------------------------------------------------------
__global__ void __launch_bounds__(256, 2)
enc_kernel(const float* __restrict__ x,
           const float* __restrict__ W1, const float* __restrict__ b1,
           const float* __restrict__ W2, const float* __restrict__ b2,
           const float* __restrict__ lg, const float* __restrict__ lb, int n) {
    __shared__ __align__(16) float sW1T[128 * 16];  // [k][j] = W1[j][k]
    __shared__ __align__(16) float sW2[128 * 64];
    __shared__ float sb1[128];
    __shared__ __align__(16) float sb2[64];
    __shared__ float sg[64], sbb[64];
    for (int i = threadIdx.x; i < 2048; i += 256) {
        int j = i >> 7, k = i & 127;
        sW1T[k * 16 + j] = W1[i];
    }
    for (int i = threadIdx.x; i < 8192; i += 256) sW2[i] = W2[i];
    if (threadIdx.x < 128) sb1[threadIdx.x] = b1[threadIdx.x];
    if (threadIdx.x < 64) {
        sb2[threadIdx.x] = b2[threadIdx.x];
        sg[threadIdx.x]  = lg[threadIdx.x];
        sbb[threadIdx.x] = lb[threadIdx.x];
    }
    __syncthreads();

    int i = blockIdx.x * 256 + threadIdx.x;
    if (i >= n) return;
    g_deg[i] = 0;   // prepare for fill_csr_kernel

    float xr[16];
    const float4* xp = reinterpret_cast<const float4*>(x + (size_t)i * 16);
    #pragma unroll
    for (int q = 0; q < 4; q++) {
        float4 v = xp[q];
        xr[4 * q] = v.x; xr[4 * q + 1] = v.y; xr[4 * q + 2] = v.z; xr[4 * q + 3] = v.w;
    }

    unsigned long long o2[32];
    const unsigned long long* sb2p = reinterpret_cast<const unsigned long long*>(sb2);
    #pragma unroll
    for (int j = 0; j < 32; j++) o2[j] = sb2p[j];

    #pragma unroll 8
    for (int k = 0; k < 128; k++) {
        const float4* c = reinterpret_cast<const float4*>(sW1T + k * 16);
        float t = sb1[k];
        #pragma unroll
        for (int q = 0; q < 4; q++) {
            float4 wv = c[q];
            t += wv.x * xr[4 * q] + wv.y * xr[4 * q + 1]
               + wv.z * xr[4 * q + 2] + wv.w * xr[4 * q + 3];
        }
        t = lrelu(t);
        unsigned long long tk = dup2(t);
        const ulonglong2* row = reinterpret_cast<const ulonglong2*>(sW2 + k * 64);
        #pragma unroll
        for (int j = 0; j < 16; j++) {
            ulonglong2 p = row[j];
            fma2(o2[2 * j],     tk, p.x);
            fma2(o2[2 * j + 1], tk, p.y);
        }
    }

    float o[64];
    #pragma unroll
    for (int j = 0; j < 32; j++) {
        float2 f = unpack2(o2[j]);
        o[2 * j] = f.x; o[2 * j + 1] = f.y;
    }

    float s = 0.f, sq = 0.f;
    #pragma unroll
    for (int k = 0; k < 64; k++) { s += o[k]; sq += o[k] * o[k]; }
    float mu  = s * (1.f / 64.f);
    float var = sq * (1.f / 64.f) - mu * mu;
    float inv = rsqrtf(var + 1e-5f);

    float4* out4 = reinterpret_cast<float4*>(g_hn + (size_t)i * 64);
    #pragma unroll
    for (int k4 = 0; k4 < 16; k4++) {
        float4 v;
        v.x = (o[4 * k4]     - mu) * inv * sg[4 * k4]     + sbb[4 * k4];
        v.y = (o[4 * k4 + 1] - mu) * inv * sg[4 * k4 + 1] + sbb[4 * k4 + 1];
        v.z = (o[4 * k4 + 2] - mu) * inv * sg[4 * k4 + 2] + sbb[4 * k4 + 2];
        v.w = (o[4 * k4 + 3] - mu) * inv * sg[4 * k4 + 3] + sbb[4 * k4 + 3];
        out4[k4] = v;
    }
}

// ---------------------------------------------------------------------------
// CSR gather, HALF-WARP per node: 16 lanes own 4 channels each (float4).
// Warp processes 2 nodes concurrently. msg[i] = sum_e w_e * hn[src_e].
// ---------------------------------------------------------------------------
__global__ void gather_kernel(int n) {
    const int lane = threadIdx.x & 31;
    const int sub  = lane >> 4;      // which node of the pair
    const int l16  = lane & 15;      // channel group (4 floats)
    int wid = (blockIdx.x * blockDim.x + threadIdx.x) >> 5;
    int i = wid * 2 + sub;
    if (i >= n) return;

    int deg = g_deg[i];
    if (deg > SLOT) deg = SLOT;
    const int4* row4 = reinterpret_cast<const int4*>(g_csr + (size_t)i * SLOT);
    const char* hb = reinterpret_cast<const char*>(g_hn) + l16 * 16;

    float ax = 0.f, ay = 0.f, az = 0.f, aw = 0.f;
    int q = 0;
    for (; q + 4 <= deg; q += 4) {
        int4 a = row4[q >> 1];
        int4 b = row4[(q >> 1) + 1];
        float4 v0 = *reinterpret_cast<const float4*>(hb + a.x);
        float4 v1 = *reinterpret_cast<const float4*>(hb + a.z);
        float4 v2 = *reinterpret_cast<const float4*>(hb + b.x);
        float4 v3 = *reinterpret_cast<const float4*>(hb + b.z);
        float w0 = __int_as_float(a.y), w1 = __int_as_float(a.w);
        float w2 = __int_as_float(b.y), w3 = __int_as_float(b.w);
        ax += w0 * v0.x + w1 * v1.x + w2 * v2.x + w3 * v3.x;
        ay += w0 * v0.y + w1 * v1.y + w2 * v2.y + w3 * v3.y;
        az += w0 * v0.z + w1 * v1.z + w2 * v2.z + w3 * v3.z;
        aw += w0 * v0.w + w1 * v1.w + w2 * v2.w + w3 * v3.w;
    }
    for (; q + 2 <= deg; q += 2) {
        int4 a = row4[q >> 1];
        float4 v0 = *reinterpret_cast<const float4*>(hb + a.x);
        float4 v1 = *reinterpret_cast<const float4*>(hb + a.z);
        float w0 = __int_as_float(a.y), w1 = __int_as_float(a.w);
        ax += w0 * v0.x + w1 * v1.x;
        ay += w0 * v0.y + w1 * v1.y;
        az += w0 * v0.z + w1 * v1.z;
        aw += w0 * v0.w + w1 * v1.w;
    }
    if (q < deg) {
        int2 e = reinterpret_cast<const int2*>(row4)[q];
        float4 v = *reinterpret_cast<const float4*>(hb + e.x);
        float w = __int_as_float(e.y);
        ax += w * v.x; ay += w * v.y; az += w * v.z; aw += w * v.w;
    }
    reinterpret_cast<float4*>(g_msg)[(size_t)i * 16 + l16] =
        make_float4(ax, ay, az, aw);
}

// ---------------------------------------------------------------------------
// Node body with CONSTANT-BANK weights: y = hn@nW + msg@eW + by;
// o = leaky(y)@mW + mb + hn   (o left in registers)
// ---------------------------------------------------------------------------
__device__ __forceinline__ void node_body_const(int i, float (&o)[64]) {
    const float4* hn4 = reinterpret_cast<const float4*>(g_hn + (size_t)i * 64);
    const float4* m4  = reinterpret_cast<const float4*>(g_msg + (size_t)i * 64);

    unsigned long long y2[16];
    #pragma unroll
    for (int j = 0; j < 16; j++)
        y2[j] = *reinterpret_cast<const unsigned long long*>(&cL[C_BY + 2 * j]);

    // y += hn @ nW
    #pragma unroll
    for (int k4 = 0; k4 < 16; k4++) {
        float4 hv = hn4[k4];
        float hc[4] = {hv.x, hv.y, hv.z, hv.w};
        #pragma unroll
        for (int c = 0; c < 4; c++) {
            unsigned long long hk = dup2(hc[c]);
            #pragma unroll
            for (int j = 0; j < 8; j++) {
                ulonglong2 p = *reinterpret_cast<const ulonglong2*>(
                    &cL[C_NW + (k4 * 4 + c) * 32 + 4 * j]);
                fma2(y2[2 * j],     hk, p.x);
                fma2(y2[2 * j + 1], hk, p.y);
            }
        }
    }

    // y += msg @ eW
    #pragma unroll
    for (int k4 = 0; k4 < 16; k4++) {
        float4 mv = m4[k4];
        float mc[4] = {mv.x, mv.y, mv.z, mv.w};
        #pragma unroll
        for (int c = 0; c < 4; c++) {
            unsigned long long mk = dup2(mc[c]);
            #pragma unroll
            for (int j = 0; j < 8; j++) {
                ulonglong2 p = *reinterpret_cast<const ulonglong2*>(
                    &cL[C_EW + (k4 * 4 + c) * 32 + 4 * j]);
                fma2(y2[2 * j],     mk, p.x);
                fma2(y2[2 * j + 1], mk, p.y);
            }
        }
    }

    float z[32];
    #pragma unroll
    for (int j = 0; j < 16; j++) {
        float2 f = unpack2(y2[j]);
        z[2 * j]     = lrelu(f.x);
        z[2 * j + 1] = lrelu(f.y);
    }

    unsigned long long o2[32];
    #pragma unroll
    for (int j = 0; j < 32; j++)
        o2[j] = *reinterpret_cast<const unsigned long long*>(&cL[C_MB + 2 * j]);

    #pragma unroll
    for (int k = 0; k < 32; k++) {
        unsigned long long zk = dup2(z[k]);
        #pragma unroll
        for (int j = 0; j < 16; j++) {
            ulonglong2 p = *reinterpret_cast<const ulonglong2*>(
                &cL[C_MW + k * 64 + 4 * j]);
            fma2(o2[2 * j],     zk, p.x);
            fma2(o2[2 * j + 1], zk, p.y);
        }
    }

    #pragma unroll
    for (int j = 0; j < 32; j++) {
        float2 f = unpack2(o2[j]);
        o[2 * j] = f.x; o[2 * j + 1] = f.y;
    }
    #pragma unroll
    for (int k4 = 0; k4 < 16; k4++) {
        float4 hv = hn4[k4];
        o[4 * k4]     += hv.x;
        o[4 * k4 + 1] += hv.y;
        o[4 * k4 + 2] += hv.z;
        o[4 * k4 + 3] += hv.w;
    }
}

// ---------------------------------------------------------------------------
// Layers 0-2: update + LN (gamma/beta from cL), writes g_hn in place
// ---------------------------------------------------------------------------
__global__ void __launch_bounds__(256)
update_kernel(int n) {
    int i = blockIdx.x * 256 + threadIdx.x;
    if (i >= n) return;

    float o[64];
    node_body_const(i, o);

    float s = 0.f, sq = 0.f;
    #pragma unroll
    for (int k = 0; k < 64; k++) { s += o[k]; sq += o[k] * o[k]; }
    float mu  = s * (1.f / 64.f);
    float var = sq * (1.f / 64.f) - mu * mu;
    float inv = rsqrtf(var + 1e-5f);

    float4* out4 = reinterpret_cast<float4*>(g_hn + (size_t)i * 64);
    #pragma unroll
    for (int k4 = 0; k4 < 16; k4++) {
        float4 v;
        v.x = (o[4 * k4]     - mu) * inv * cL[C_G + 4 * k4]     + cL[C_B + 4 * k4];
        v.y = (o[4 * k4 + 1] - mu) * inv * cL[C_G + 4 * k4 + 1] + cL[C_B + 4 * k4 + 1];
        v.z = (o[4 * k4 + 2] - mu) * inv * cL[C_G + 4 * k4 + 2] + cL[C_B + 4 * k4 + 2];
        v.w = (o[4 * k4 + 3] - mu) * inv * cL[C_G + 4 * k4 + 3] + cL[C_B + 4 * k4 + 3];
        out4[k4] = v;
    }
}

// ---------------------------------------------------------------------------
// Layer 3 + decoder (decoder weights from cD)
// ---------------------------------------------------------------------------
__global__ void __launch_bounds__(256)
update_dec_kernel(float* __restrict__ out, int n) {
    int i = blockIdx.x * 256 + threadIdx.x;
    if (i >= n) return;

    float o[64];
    node_body_const(i, o);

    unsigned long long hp[32];
    #pragma unroll
    for (int q = 0; q < 32; q++) hp[q] = pack2(o[2 * q], o[2 * q + 1]);

    float t[24];
    #pragma unroll
    for (int j = 0; j < 24; j++) {
        unsigned long long acc = 0ULL;
        #pragma unroll
        for (int m = 0; m < 16; m++) {
            ulonglong2 p = *reinterpret_cast<const ulonglong2*>(&cD[j * 64 + 4 * m]);
            fma2(acc, hp[2 * m],     p.x);
            fma2(acc, hp[2 * m + 1], p.y);
        }
        float2 f = unpack2(acc);
        t[j] = lrelu(cD[1608 + j] + f.x + f.y);
    }

    #pragma unroll
    for (int c = 0; c < 3; c++) {
        float oo = cD[1632 + c];
        #pragma unroll
        for (int j = 0; j < 24; j++) oo += t[j] * cD[1536 + c * 24 + j];
        out[(size_t)i * 3 + c] = oo;
    }
}

// ---------------------------------------------------------------------------
extern "C" void kernel_launch(void* const* d_in, const int* in_sizes, int n_in,
                              void* d_out, int out_size) {
    const float* x       = (const float*)d_in[0];
    // d_in[1] = pos (unused by reference)
    const int*   esrc    = (const int*)  d_in[2];
    const int*   edst    = (const int*)  d_in[3];
    const float* ew      = (const float*)d_in[4];
    const float* enc_W1  = (const float*)d_in[5];
    const float* enc_b1  = (const float*)d_in[6];
    const float* enc_W2  = (const float*)d_in[7];
    const float* enc_b2  = (const float*)d_in[8];
    const float* dec_W1  = (const float*)d_in[9];
    const float* dec_b1  = (const float*)d_in[10];
    const float* dec_W2  = (const float*)d_in[11];
    const float* dec_b2  = (const float*)d_in[12];
    const float* ln_g    = (const float*)d_in[13];
    const float* ln_b    = (const float*)d_in[14];
    const float* node_W  = (const float*)d_in[15];
    const float* node_b  = (const float*)d_in[16];
    const float* edge_W  = (const float*)d_in[17];
    const float* edge_b  = (const float*)d_in[18];
    const float* mlp_W   = (const float*)d_in[19];
    const float* mlp_b   = (const float*)d_in[20];

    const int n  = in_sizes[0] / 16;   // 100000 nodes
    const int ne = in_sizes[2];        // 1200000 edges

    const int nb = (n + 255) / 256;
    const int fe = (ne + 255) / 256;
    const int ga = (n + 15) / 16;      // half-warp per node, 256 threads/block
    const int pk = (4 * LPACK + 1636 + 255) / 256;

    float* packL = nullptr;
    cudaGetSymbolAddress((void**)&packL, g_packL);
    float* packD = nullptr;
    cudaGetSymbolAddress((void**)&packD, g_packD);

    // pack weights, run encoder (also zeroes g_deg), build CSR
    pack_kernel<<<pk, 256>>>(node_W, node_b, edge_W, edge_b, mlp_W, mlp_b,
                             ln_g, ln_b, dec_W1, dec_b1, dec_W2, dec_b2);
    enc_kernel<<<nb, 256>>>(x, enc_W1, enc_b1, enc_W2, enc_b2, ln_g, ln_b, n);
    fill_csr_kernel<<<fe, 256>>>(esrc, edst, ew, ne);

    // decoder constants (used only by the last kernel)
    cudaMemcpyToSymbolAsync(cD, packD, 1636 * sizeof(float), 0,
                            cudaMemcpyDeviceToDevice, 0);

    for (int l = 0; l < 3; l++) {
        cudaMemcpyToSymbolAsync(cL, packL + (size_t)l * LPACK, LPACK * sizeof(float),
                                0, cudaMemcpyDeviceToDevice, 0);
        gather_kernel<<<ga, 256>>>(n);
        update_kernel<<<nb, 256>>>(n);
    }

    cudaMemcpyToSymbolAsync(cL, packL + (size_t)3 * LPACK, LPACK * sizeof(float),
                            0, cudaMemcpyDeviceToDevice, 0);
    gather_kernel<<<ga, 256>>>(n);
    update_dec_kernel<<<nb, 256>>>((float*)d_out, n);
}